// round 4
// baseline (speedup 1.0000x reference)
#include <cuda_runtime.h>
#include <cuda_bf16.h>
#include <math.h>
#include <stdint.h>

// ---------------- scratch (static device arrays; no allocation) ----------------
__device__ float g_qkv[16384 * 1536];      // QKV projection output
__device__ float g_scores[64 * 512 * 512]; // attention scores / probs
__device__ float g_attn[16384 * 512];      // attention output (pre out-proj)
__device__ float g_dec[16384 * 512];       // decoder features after ReLU
__device__ float g_em[16384 * 24];         // CRF emissions
__device__ float g_llh[32];                // per-batch (num - den)

// ---------------- tf32 split helper (hi/lo, ~2^-22 combined precision) --------
__device__ __forceinline__ void split_tf32(float x, uint32_t& h, uint32_t& l)
{
    uint32_t hu;
    asm("cvt.rna.tf32.f32 %0, %1;" : "=r"(hu) : "f"(x));
    float hf = __uint_as_float(hu);
    float lf = x - hf;
    uint32_t lu;
    asm("cvt.rna.tf32.f32 %0, %1;" : "=r"(lu) : "f"(lf));
    h = hu; l = lu;
}

#define MMA_TF32(d, a, b0, b1)                                              \
    asm("mma.sync.aligned.m16n8k8.row.col.f32.tf32.tf32.f32 "               \
        "{%0,%1,%2,%3}, {%4,%5,%6,%7}, {%8,%9}, {%0,%1,%2,%3};"             \
        : "+f"(d[0]), "+f"(d[1]), "+f"(d[2]), "+f"(d[3])                    \
        : "r"(a[0]), "r"(a[1]), "r"(a[2]), "r"(a[3]), "r"(b0), "r"(b1))

// ---------------- tf32x3 GEMM: C = act(alpha * A @ op(B) + bias) ---------------
// A: MxK row-major (lda). op(B): TRANSB ? B is NxK : B is KxN.
// Batched via z: ptr += (z/zdiv)*outer + (z%zdiv)*inner.
// Tile: 128x128xBK16. 8 warps as 2x4, each warp 64x32 (4x4 m16n8 tiles).
#define GBM 128
#define GBN 128
#define GBK 16
#define SMS 136   // smem row stride (words): 8c+r covers all banks -> conflict-free

__global__ __launch_bounds__(256, 1) void mma_gemm_kernel(
    const float* __restrict__ A, int lda, long long aOuter, long long aInner,
    const float* __restrict__ B, int ldb, long long bOuter, long long bInner,
    float* __restrict__ C, int ldc, long long cOuter, long long cInner,
    const float* __restrict__ bias,
    int M, int N, int K, float alpha, int flags, int zdiv)
{
    int z = blockIdx.z;
    A += (long long)(z / zdiv) * aOuter + (long long)(z % zdiv) * aInner;
    B += (long long)(z / zdiv) * bOuter + (long long)(z % zdiv) * bInner;
    C += (long long)(z / zdiv) * cOuter + (long long)(z % zdiv) * cInner;

    __shared__ uint32_t Ah[GBK][SMS], Al[GBK][SMS];
    __shared__ uint32_t Bh[GBK][SMS], Bl[GBK][SMS];

    int tid = threadIdx.x;
    int lane = tid & 31;
    int w = tid >> 5;
    int r = lane >> 2;        // 0..7
    int cq = lane & 3;        // 0..3
    int wm = (w >> 2) * 64;   // warp m offset within tile
    int wn = (w & 3) * 32;    // warp n offset within tile
    int bm = blockIdx.y * GBM, bn = blockIdx.x * GBN;
    bool transB = (flags & 1) != 0;

    float acc[4][4][4];
#pragma unroll
    for (int i = 0; i < 4; i++)
#pragma unroll
        for (int j = 0; j < 4; j++)
#pragma unroll
            for (int q = 0; q < 4; q++) acc[i][j][q] = 0.f;

    for (int k0 = 0; k0 < K; k0 += GBK) {
        // ---- load + split A tile (GBM x GBK) into Ah/Al[k][m] ----
#pragma unroll
        for (int it = 0; it < 2; it++) {
            int flat = tid + it * 256;
            int row = flat >> 2;
            int c4 = (flat & 3) * 4;
            float4 v = *(const float4*)&A[(long long)(bm + row) * lda + k0 + c4];
            float pv[4] = {v.x, v.y, v.z, v.w};
#pragma unroll
            for (int q = 0; q < 4; q++) {
                uint32_t h, l;
                split_tf32(pv[q], h, l);
                Ah[c4 + q][row] = h;
                Al[c4 + q][row] = l;
            }
        }
        // ---- load + split B tile into Bh/Bl[k][n] ----
        if (transB) {
#pragma unroll
            for (int it = 0; it < 2; it++) {
                int flat = tid + it * 256;
                int row = flat >> 2;
                int c4 = (flat & 3) * 4;
                float4 v = *(const float4*)&B[(long long)(bn + row) * ldb + k0 + c4];
                float pv[4] = {v.x, v.y, v.z, v.w};
#pragma unroll
                for (int q = 0; q < 4; q++) {
                    uint32_t h, l;
                    split_tf32(pv[q], h, l);
                    Bh[c4 + q][row] = h;
                    Bl[c4 + q][row] = l;
                }
            }
        } else {
#pragma unroll
            for (int it = 0; it < 2; it++) {
                int flat = tid + it * 256;
                int kk = flat >> 5;
                int n4 = (flat & 31) * 4;
                float4 v = *(const float4*)&B[(long long)(k0 + kk) * ldb + bn + n4];
                float pv[4] = {v.x, v.y, v.z, v.w};
#pragma unroll
                for (int q = 0; q < 4; q++) {
                    uint32_t h, l;
                    split_tf32(pv[q], h, l);
                    Bh[kk][n4 + q] = h;
                    Bl[kk][n4 + q] = l;
                }
            }
        }
        __syncthreads();

#pragma unroll
        for (int ks = 0; ks < GBK; ks += 8) {
            uint32_t afh[4][4], afl[4][4];
#pragma unroll
            for (int i = 0; i < 4; i++) {
                int m0 = wm + 16 * i;
                afh[i][0] = Ah[ks + cq][m0 + r];
                afh[i][1] = Ah[ks + cq][m0 + r + 8];
                afh[i][2] = Ah[ks + cq + 4][m0 + r];
                afh[i][3] = Ah[ks + cq + 4][m0 + r + 8];
                afl[i][0] = Al[ks + cq][m0 + r];
                afl[i][1] = Al[ks + cq][m0 + r + 8];
                afl[i][2] = Al[ks + cq + 4][m0 + r];
                afl[i][3] = Al[ks + cq + 4][m0 + r + 8];
            }
#pragma unroll
            for (int j = 0; j < 4; j++) {
                int n0 = wn + 8 * j;
                uint32_t bh0 = Bh[ks + cq][n0 + r];
                uint32_t bh1 = Bh[ks + cq + 4][n0 + r];
                uint32_t bl0 = Bl[ks + cq][n0 + r];
                uint32_t bl1 = Bl[ks + cq + 4][n0 + r];
#pragma unroll
                for (int i = 0; i < 4; i++) {
                    MMA_TF32(acc[i][j], afh[i], bh0, bh1);  // hi * hi
                    MMA_TF32(acc[i][j], afl[i], bh0, bh1);  // lo * hi
                    MMA_TF32(acc[i][j], afh[i], bl0, bl1);  // hi * lo
                }
            }
        }
        __syncthreads();
    }

    // ---- epilogue ----
    bool relu = (flags & 2) != 0;
#pragma unroll
    for (int i = 0; i < 4; i++) {
        int row0 = bm + wm + 16 * i + r;
#pragma unroll
        for (int j = 0; j < 4; j++) {
            int col0 = bn + wn + 8 * j + 2 * cq;
            float bv0 = bias ? bias[col0] : 0.f;
            float bv1 = bias ? bias[col0 + 1] : 0.f;
            float v0 = alpha * acc[i][j][0] + bv0;
            float v1 = alpha * acc[i][j][1] + bv1;
            float v2 = alpha * acc[i][j][2] + bv0;
            float v3 = alpha * acc[i][j][3] + bv1;
            if (relu) {
                v0 = fmaxf(v0, 0.f); v1 = fmaxf(v1, 0.f);
                v2 = fmaxf(v2, 0.f); v3 = fmaxf(v3, 0.f);
            }
            *(float2*)&C[(long long)row0 * ldc + col0] = make_float2(v0, v1);
            *(float2*)&C[(long long)(row0 + 8) * ldc + col0] = make_float2(v2, v3);
        }
    }
}

// ---------------- row softmax over 512 columns (warp per row) ----------------
__global__ __launch_bounds__(256) void softmax_rows(float* __restrict__ s)
{
    int row = blockIdx.x * 8 + (threadIdx.x >> 5);
    int lane = threadIdx.x & 31;
    float* p = s + (long long)row * 512;

    float v[16];
    float m = -1e30f;
#pragma unroll
    for (int i = 0; i < 16; i++) {
        v[i] = p[lane + 32 * i];
        m = fmaxf(m, v[i]);
    }
#pragma unroll
    for (int off = 16; off; off >>= 1) m = fmaxf(m, __shfl_xor_sync(0xffffffffu, m, off));
    float sum = 0.f;
#pragma unroll
    for (int i = 0; i < 16; i++) {
        v[i] = expf(v[i] - m);   // accurate exp: Viterbi-upstream
        sum += v[i];
    }
#pragma unroll
    for (int off = 16; off; off >>= 1) sum += __shfl_xor_sync(0xffffffffu, sum, off);
    float inv = 1.f / sum;
#pragma unroll
    for (int i = 0; i < 16; i++) p[lane + 32 * i] = v[i] * inv;
}

// ---------------- emissions (24 CRF logits) + 2-class log-softmax head --------
__global__ __launch_bounds__(256) void emissions_kernel(
    const float* __restrict__ dec,
    const float* __restrict__ crf_w, const float* __restrict__ crf_b,
    const float* __restrict__ ent_w, const float* __restrict__ ent_b,
    float* __restrict__ em, float* __restrict__ seg_out)
{
    int row = blockIdx.x * 8 + (threadIdx.x >> 5);
    int lane = threadIdx.x & 31;
    const float* a = dec + (long long)row * 512;

    float acc[26];
#pragma unroll
    for (int o = 0; o < 26; o++) acc[o] = 0.f;

    for (int kk = lane; kk < 512; kk += 32) {
        float av = a[kk];
#pragma unroll
        for (int o = 0; o < 24; o++) acc[o] += av * crf_w[o * 512 + kk];
        acc[24] += av * ent_w[kk];
        acc[25] += av * ent_w[512 + kk];
    }
#pragma unroll
    for (int o = 0; o < 26; o++) {
#pragma unroll
        for (int off = 16; off; off >>= 1) acc[o] += __shfl_down_sync(0xffffffffu, acc[o], off);
    }
    if (lane == 0) {
#pragma unroll
        for (int o = 0; o < 24; o++) em[(long long)row * 24 + o] = acc[o] + crf_b[o];
        float z0 = acc[24] + ent_b[0];
        float z1 = acc[25] + ent_b[1];
        float m = fmaxf(z0, z1);
        float l = m + logf(expf(z0 - m) + expf(z1 - m));
        seg_out[(long long)row * 2 + 0] = z0 - l;
        seg_out[(long long)row * 2 + 1] = z1 - l;
    }
}

// ---------------- CRF: numerator + forward (logsumexp) + Viterbi --------------
__global__ __launch_bounds__(64) void crf_kernel(
    const float* __restrict__ em, const int* __restrict__ labels,
    const float* __restrict__ start_t, const float* __restrict__ end_t,
    const float* __restrict__ trans,
    float* __restrict__ out_crf, float* __restrict__ llh_part)
{
    __shared__ float tr[24 * 24];
    __shared__ float lse[24], vit[24];
    __shared__ unsigned char hist[511 * 24];
    __shared__ float red[64];
    __shared__ float s_num;

    int b = blockIdx.x, tid = threadIdx.x;
    const float* e0 = em + (long long)b * 512 * 24;
    const int* lab = labels + b * 512;

    for (int i = tid; i < 576; i += 64) tr[i] = trans[i];
    __syncthreads();

    float local = 0.f;
    for (int t = 1 + tid; t < 512; t += 64) {
        int lp = lab[t - 1], lc = lab[t];
        local += tr[lp * 24 + lc] + e0[t * 24 + lc];
    }
    red[tid] = local;
    if (tid < 24) { float v = start_t[tid] + e0[tid]; lse[tid] = v; vit[tid] = v; }
    __syncthreads();
    if (tid == 0) {
        float s = 0.f;
        for (int i = 0; i < 64; i++) s += red[i];
        int l0 = lab[0], lN = lab[511];
        s_num = s + start_t[l0] + e0[l0] + end_t[lN];
    }
    __syncthreads();

    for (int t = 1; t < 512; t++) {
        const float* e = e0 + t * 24;
        float nl = 0.f, nv = 0.f;
        int bi = 0;
        if (tid < 24) {
            int j = tid;
            float m = -1e30f;
#pragma unroll
            for (int i = 0; i < 24; i++) m = fmaxf(m, lse[i] + tr[i * 24 + j]);
            float s = 0.f;
#pragma unroll
            for (int i = 0; i < 24; i++) s += __expf(lse[i] + tr[i * 24 + j] - m);
            nl = m + __logf(s) + e[j];
        } else if (tid >= 32 && tid < 56) {
            int j = tid - 32;
            float bm = -1e30f;
#pragma unroll
            for (int i = 0; i < 24; i++) {
                float v = vit[i] + tr[i * 24 + j];
                if (v > bm) { bm = v; bi = i; }   // strict > : first-max like jnp.argmax
            }
            nv = bm + e[j];
        }
        __syncthreads();
        if (tid < 24) lse[tid] = nl;
        else if (tid >= 32 && tid < 56) {
            vit[tid - 32] = nv;
            hist[(t - 1) * 24 + (tid - 32)] = (unsigned char)bi;
        }
        __syncthreads();
    }

    if (tid == 0) {
        float m = -1e30f;
        for (int j = 0; j < 24; j++) m = fmaxf(m, lse[j] + end_t[j]);
        float s = 0.f;
        for (int j = 0; j < 24; j++) s += __expf(lse[j] + end_t[j] - m);
        float den = m + __logf(s);
        llh_part[b] = s_num - den;
    }
    if (tid == 32) {
        float bm = -1e30f;
        int last = 0;
        for (int j = 0; j < 24; j++) {
            float v = vit[j] + end_t[j];
            if (v > bm) { bm = v; last = j; }
        }
        out_crf[b * 512 + 511] = (float)last;
        int tag = last;
        for (int t = 510; t >= 0; t--) {
            tag = hist[t * 24 + tag];
            out_crf[b * 512 + t] = (float)tag;
        }
    }
}

__global__ void finalize_kernel(const float* __restrict__ llh_part, float* __restrict__ out_scalar)
{
    if (threadIdx.x == 0) {
        float s = 0.f;
        for (int i = 0; i < 32; i++) s += llh_part[i];
        *out_scalar = -s / 16384.0f;
    }
}

// --------------------------------- launch -------------------------------------
extern "C" void kernel_launch(void* const* d_in, const int* in_sizes, int n_in,
                              void* d_out, int out_size)
{
    const float* enc     = (const float*)d_in[0];   // (32,512,512)
    const int*   labels  = (const int*)d_in[1];     // (32,512)
    // d_in[2] = mask (all ones) — unused
    const float* Win     = (const float*)d_in[3];   // (1536,512)
    const float* bin_    = (const float*)d_in[4];   // (1536,)
    const float* Wout    = (const float*)d_in[5];   // (512,512)
    const float* bout    = (const float*)d_in[6];   // (512,)
    const float* crf_w   = (const float*)d_in[7];   // (24,512)
    const float* crf_b   = (const float*)d_in[8];   // (24,)
    const float* start_t = (const float*)d_in[9];   // (24,)
    const float* end_t   = (const float*)d_in[10];  // (24,)
    const float* trans   = (const float*)d_in[11];  // (24,24)
    const float* ent_w   = (const float*)d_in[12];  // (2,512)
    const float* ent_b   = (const float*)d_in[13];  // (2,)

    float* out = (float*)d_out;  // [crf_out 16384 | seg_out 32768 | -llh 1]

    float *qkv, *scores, *attn, *dec, *em, *llh;
    cudaGetSymbolAddress((void**)&qkv, g_qkv);
    cudaGetSymbolAddress((void**)&scores, g_scores);
    cudaGetSymbolAddress((void**)&attn, g_attn);
    cudaGetSymbolAddress((void**)&dec, g_dec);
    cudaGetSymbolAddress((void**)&em, g_em);
    cudaGetSymbolAddress((void**)&llh, g_llh);

    // 1) QKV = enc @ Win^T + bin : (16384 x 1536), K=512
    mma_gemm_kernel<<<dim3(1536 / GBN, 16384 / GBM, 1), 256>>>(
        enc, 512, 0, 0,
        Win, 512, 0, 0,
        qkv, 1536, 0, 0,
        bin_, 16384, 1536, 512, 1.0f, /*transB*/1, 1);

    // 2) scores[b,h] = Q @ K^T / 16 : 64 batched (512 x 512), K=256
    mma_gemm_kernel<<<dim3(512 / GBN, 512 / GBM, 64), 256>>>(
        qkv,        1536, 512LL * 1536, 256,
        qkv + 512,  1536, 512LL * 1536, 256,
        scores,     512,  524288LL,     262144LL,
        nullptr, 512, 512, 256, 0.0625f, /*transB*/1, 2);

    // 3) softmax over rows
    softmax_rows<<<4096, 256>>>(scores);

    // 4) attn_out[b,h] = P @ V : 64 batched (512 x 256), K=512
    mma_gemm_kernel<<<dim3(256 / GBN, 512 / GBM, 64), 256>>>(
        scores,      512,  524288LL,     262144LL,
        qkv + 1024,  1536, 512LL * 1536, 256,
        attn,        512,  262144LL,     256LL,
        nullptr, 512, 256, 512, 1.0f, /*transB*/0, 2);

    // 5) dec = relu(attn @ Wout^T + bout) : (16384 x 512), K=512
    mma_gemm_kernel<<<dim3(512 / GBN, 16384 / GBM, 1), 256>>>(
        attn, 512, 0, 0,
        Wout, 512, 0, 0,
        dec,  512, 0, 0,
        bout, 16384, 512, 512, 1.0f, /*transB|relu*/3, 1);

    // 6) emissions (24) + seg log-softmax (2); seg written straight into d_out
    emissions_kernel<<<2048, 256>>>(dec, crf_w, crf_b, ent_w, ent_b, em, out + 16384);

    // 7) CRF scan: numerator + normalizer + Viterbi (+ backtrack into d_out)
    crf_kernel<<<32, 64>>>(em, labels, start_t, end_t, trans, out, llh);

    // 8) scalar -llh
    finalize_kernel<<<1, 32>>>(llh, out + 16384 + 32768);
}

// round 6
// speedup vs baseline: 1.2531x; 1.2531x over previous
#include <cuda_runtime.h>
#include <cuda_bf16.h>
#include <math.h>
#include <stdint.h>

// ---------------- scratch (static device arrays; no allocation) ----------------
__device__ float g_qkv[16384 * 1536];      // QKV projection output
__device__ float g_scores[64 * 512 * 512]; // attention scores / probs
__device__ float g_attn[16384 * 512];      // attention output (pre out-proj)
__device__ float g_dec[16384 * 512];       // decoder features after ReLU
__device__ float g_em[16384 * 24];         // CRF emissions
__device__ float g_llh[32];                // per-batch (num - den)

// ---------------- tf32 split helper (hi/lo, ~2^-22 combined precision) --------
__device__ __forceinline__ void split_tf32(float x, uint32_t& h, uint32_t& l)
{
    uint32_t hu;
    asm("cvt.rna.tf32.f32 %0, %1;" : "=r"(hu) : "f"(x));
    float lf = x - __uint_as_float(hu);
    uint32_t lu;
    asm("cvt.rna.tf32.f32 %0, %1;" : "=r"(lu) : "f"(lf));
    h = hu; l = lu;
}

#define MMA_TF32(d, a, b0, b1)                                              \
    asm("mma.sync.aligned.m16n8k8.row.col.f32.tf32.tf32.f32 "               \
        "{%0,%1,%2,%3}, {%4,%5,%6,%7}, {%8,%9}, {%0,%1,%2,%3};"             \
        : "+f"(d[0]), "+f"(d[1]), "+f"(d[2]), "+f"(d[3])                    \
        : "r"(a[0]), "r"(a[1]), "r"(a[2]), "r"(a[3]), "r"(b0), "r"(b1))

// ---------------- tf32x3 GEMM: C = act(alpha * A @ op(B) + bias) ---------------
// A: MxK row-major (lda). op(B): TRANSB ? B is NxK : B is KxN.
// Batched via z: ptr += (z/zdiv)*outer + (z%zdiv)*inner.
// Tile: 128x128x16. 8 warps as 2x4, each warp 64x32 (4x4 m16n8 tiles).
// Double-buffered SMEM + register prefetch of the next chunk during MMA.
#define GBM 128
#define GBN 128
#define GBK 16
#define SMS 136                    // smem row stride (words) -> conflict-free frags
#define STAGE_WORDS (4 * GBK * SMS)   // Ah | Al | Bh | Bl
#define SMEM_BYTES (2 * STAGE_WORDS * 4)

__global__ __launch_bounds__(256, 1) void mma_gemm_kernel(
    const float* __restrict__ A, int lda, long long aOuter, long long aInner,
    const float* __restrict__ B, int ldb, long long bOuter, long long bInner,
    float* __restrict__ C, int ldc, long long cOuter, long long cInner,
    const float* __restrict__ bias,
    int K, float alpha, int flags, int zdiv)
{
    extern __shared__ uint32_t sm[];
    int z = blockIdx.z;
    A += (long long)(z / zdiv) * aOuter + (long long)(z % zdiv) * aInner;
    B += (long long)(z / zdiv) * bOuter + (long long)(z % zdiv) * bInner;
    C += (long long)(z / zdiv) * cOuter + (long long)(z % zdiv) * cInner;

    int tid = threadIdx.x;
    int lane = tid & 31;
    int w = tid >> 5;
    int r = lane >> 2;        // 0..7
    int cq = lane & 3;        // 0..3
    int wm = (w >> 2) * 64;   // warp m offset
    int wn = (w & 3) * 32;    // warp n offset
    int bm = blockIdx.y * GBM, bn = blockIdx.x * GBN;
    bool transB = (flags & 1) != 0;

    // per-thread load coordinates (2 float4 each for A and B)
    int aRow0 = tid >> 2,         aCol0 = (tid & 3) * 4;
    int aRow1 = (tid + 256) >> 2, aCol1 = (tid & 3) * 4;   // (tid+256)&3 == tid&3
    int bKk0 = tid >> 5,          bN40 = (tid & 31) * 4;
    int bKk1 = (tid + 256) >> 5,  bN41 = (tid & 31) * 4;

    float acc[4][4][4];
#pragma unroll
    for (int i = 0; i < 4; i++)
#pragma unroll
        for (int j = 0; j < 4; j++)
#pragma unroll
            for (int q = 0; q < 4; q++) acc[i][j][q] = 0.f;

    float4 pa0, pa1, pb0, pb1;

#define LOAD_CHUNK(c) do {                                                          \
    pa0 = *(const float4*)&A[(long long)(bm + aRow0) * lda + (c) * GBK + aCol0];    \
    pa1 = *(const float4*)&A[(long long)(bm + aRow1) * lda + (c) * GBK + aCol1];    \
    if (transB) {                                                                   \
        pb0 = *(const float4*)&B[(long long)(bn + aRow0) * ldb + (c) * GBK + aCol0];\
        pb1 = *(const float4*)&B[(long long)(bn + aRow1) * ldb + (c) * GBK + aCol1];\
    } else {                                                                        \
        pb0 = *(const float4*)&B[(long long)((c) * GBK + bKk0) * ldb + bn + bN40];  \
        pb1 = *(const float4*)&B[(long long)((c) * GBK + bKk1) * ldb + bn + bN41];  \
    }                                                                               \
} while (0)

#define SPLIT4(dstH, dstL, vec, idxfn) do {                                         \
    float _pv[4] = {(vec).x, (vec).y, (vec).z, (vec).w};                            \
    _Pragma("unroll")                                                               \
    for (int q = 0; q < 4; q++) {                                                   \
        uint32_t _h, _l;                                                            \
        split_tf32(_pv[q], _h, _l);                                                 \
        int _ix = idxfn;                                                            \
        (dstH)[_ix] = _h; (dstL)[_ix] = _l;                                         \
    }                                                                               \
} while (0)

#define STORE_CHUNK(base) do {                                                      \
    uint32_t* sAh = (base);                                                         \
    uint32_t* sAl = (base) + GBK * SMS;                                             \
    uint32_t* sBh = (base) + 2 * GBK * SMS;                                         \
    uint32_t* sBl = (base) + 3 * GBK * SMS;                                         \
    SPLIT4(sAh, sAl, pa0, (aCol0 + q) * SMS + aRow0);                               \
    SPLIT4(sAh, sAl, pa1, (aCol1 + q) * SMS + aRow1);                               \
    if (transB) {                                                                   \
        SPLIT4(sBh, sBl, pb0, (aCol0 + q) * SMS + aRow0);                           \
        SPLIT4(sBh, sBl, pb1, (aCol1 + q) * SMS + aRow1);                           \
    } else {                                                                        \
        SPLIT4(sBh, sBl, pb0, bKk0 * SMS + bN40 + q);                               \
        SPLIT4(sBh, sBl, pb1, bKk1 * SMS + bN41 + q);                               \
    }                                                                               \
} while (0)

    int nk = K / GBK;

    // prologue: chunk 0 -> buffer 0
    LOAD_CHUNK(0);
    STORE_CHUNK(sm);
    __syncthreads();

    for (int c = 0; c < nk; c++) {
        // prefetch next chunk into registers (overlaps with MMA below)
        if (c + 1 < nk) LOAD_CHUNK(c + 1);

        uint32_t* base = sm + (c & 1) * STAGE_WORDS;
        uint32_t* sAh = base;
        uint32_t* sAl = base + GBK * SMS;
        uint32_t* sBh = base + 2 * GBK * SMS;
        uint32_t* sBl = base + 3 * GBK * SMS;

#pragma unroll
        for (int ks = 0; ks < GBK; ks += 8) {
            uint32_t afh[4][4], afl[4][4];
#pragma unroll
            for (int i = 0; i < 4; i++) {
                int m0 = wm + 16 * i;
                afh[i][0] = sAh[(ks + cq) * SMS + m0 + r];
                afh[i][1] = sAh[(ks + cq) * SMS + m0 + r + 8];
                afh[i][2] = sAh[(ks + cq + 4) * SMS + m0 + r];
                afh[i][3] = sAh[(ks + cq + 4) * SMS + m0 + r + 8];
                afl[i][0] = sAl[(ks + cq) * SMS + m0 + r];
                afl[i][1] = sAl[(ks + cq) * SMS + m0 + r + 8];
                afl[i][2] = sAl[(ks + cq + 4) * SMS + m0 + r];
                afl[i][3] = sAl[(ks + cq + 4) * SMS + m0 + r + 8];
            }
#pragma unroll
            for (int j = 0; j < 4; j++) {
                int n0 = wn + 8 * j;
                uint32_t bh0 = sBh[(ks + cq) * SMS + n0 + r];
                uint32_t bh1 = sBh[(ks + cq + 4) * SMS + n0 + r];
                uint32_t bl0 = sBl[(ks + cq) * SMS + n0 + r];
                uint32_t bl1 = sBl[(ks + cq + 4) * SMS + n0 + r];
#pragma unroll
                for (int i = 0; i < 4; i++) {
                    MMA_TF32(acc[i][j], afh[i], bh0, bh1);  // hi * hi
                    MMA_TF32(acc[i][j], afl[i], bh0, bh1);  // lo * hi
                    MMA_TF32(acc[i][j], afh[i], bl0, bl1);  // hi * lo
                }
            }
        }
        __syncthreads();
        if (c + 1 < nk) {
            STORE_CHUNK(sm + ((c + 1) & 1) * STAGE_WORDS);
            __syncthreads();
        }
    }

    // ---- epilogue ----
    bool relu = (flags & 2) != 0;
#pragma unroll
    for (int i = 0; i < 4; i++) {
        int row0 = bm + wm + 16 * i + r;
#pragma unroll
        for (int j = 0; j < 4; j++) {
            int col0 = bn + wn + 8 * j + 2 * cq;
            float bv0 = bias ? bias[col0] : 0.f;
            float bv1 = bias ? bias[col0 + 1] : 0.f;
            float v0 = alpha * acc[i][j][0] + bv0;
            float v1 = alpha * acc[i][j][1] + bv1;
            float v2 = alpha * acc[i][j][2] + bv0;
            float v3 = alpha * acc[i][j][3] + bv1;
            if (relu) {
                v0 = fmaxf(v0, 0.f); v1 = fmaxf(v1, 0.f);
                v2 = fmaxf(v2, 0.f); v3 = fmaxf(v3, 0.f);
            }
            *(float2*)&C[(long long)row0 * ldc + col0] = make_float2(v0, v1);
            *(float2*)&C[(long long)(row0 + 8) * ldc + col0] = make_float2(v2, v3);
        }
    }
#undef LOAD_CHUNK
#undef SPLIT4
#undef STORE_CHUNK
}

// ---------------- row softmax over 512 columns (warp per row) ----------------
__global__ __launch_bounds__(256) void softmax_rows(float* __restrict__ s)
{
    int row = blockIdx.x * 8 + (threadIdx.x >> 5);
    int lane = threadIdx.x & 31;
    float* p = s + (long long)row * 512;

    float v[16];
    float m = -1e30f;
#pragma unroll
    for (int i = 0; i < 16; i++) {
        v[i] = p[lane + 32 * i];
        m = fmaxf(m, v[i]);
    }
#pragma unroll
    for (int off = 16; off; off >>= 1) m = fmaxf(m, __shfl_xor_sync(0xffffffffu, m, off));
    float sum = 0.f;
#pragma unroll
    for (int i = 0; i < 16; i++) {
        v[i] = expf(v[i] - m);   // accurate exp: Viterbi-upstream
        sum += v[i];
    }
#pragma unroll
    for (int off = 16; off; off >>= 1) sum += __shfl_xor_sync(0xffffffffu, sum, off);
    float inv = 1.f / sum;
#pragma unroll
    for (int i = 0; i < 16; i++) p[lane + 32 * i] = v[i] * inv;
}

// ---------------- emissions (24 CRF logits) + 2-class log-softmax head --------
__global__ __launch_bounds__(256) void emissions_kernel(
    const float* __restrict__ dec,
    const float* __restrict__ crf_w, const float* __restrict__ crf_b,
    const float* __restrict__ ent_w, const float* __restrict__ ent_b,
    float* __restrict__ em, float* __restrict__ seg_out)
{
    int row = blockIdx.x * 8 + (threadIdx.x >> 5);
    int lane = threadIdx.x & 31;
    const float* a = dec + (long long)row * 512;

    float acc[26];
#pragma unroll
    for (int o = 0; o < 26; o++) acc[o] = 0.f;

    for (int kk = lane; kk < 512; kk += 32) {
        float av = a[kk];
#pragma unroll
        for (int o = 0; o < 24; o++) acc[o] += av * crf_w[o * 512 + kk];
        acc[24] += av * ent_w[kk];
        acc[25] += av * ent_w[512 + kk];
    }
#pragma unroll
    for (int o = 0; o < 26; o++) {
#pragma unroll
        for (int off = 16; off; off >>= 1) acc[o] += __shfl_down_sync(0xffffffffu, acc[o], off);
    }
    if (lane == 0) {
#pragma unroll
        for (int o = 0; o < 24; o++) em[(long long)row * 24 + o] = acc[o] + crf_b[o];
        float z0 = acc[24] + ent_b[0];
        float z1 = acc[25] + ent_b[1];
        float m = fmaxf(z0, z1);
        float l = m + logf(expf(z0 - m) + expf(z1 - m));
        seg_out[(long long)row * 2 + 0] = z0 - l;
        seg_out[(long long)row * 2 + 1] = z1 - l;
    }
}

// ---------------- CRF: numerator + forward (logsumexp) + Viterbi --------------
__global__ __launch_bounds__(64) void crf_kernel(
    const float* __restrict__ em, const int* __restrict__ labels,
    const float* __restrict__ start_t, const float* __restrict__ end_t,
    const float* __restrict__ trans,
    float* __restrict__ out_crf, float* __restrict__ llh_part)
{
    __shared__ float tr[24 * 24];
    __shared__ float lse[24], vit[24];
    __shared__ unsigned char hist[511 * 24];
    __shared__ float red[64];
    __shared__ float s_num;

    int b = blockIdx.x, tid = threadIdx.x;
    const float* e0 = em + (long long)b * 512 * 24;
    const int* lab = labels + b * 512;

    for (int i = tid; i < 576; i += 64) tr[i] = trans[i];
    __syncthreads();

    float local = 0.f;
    for (int t = 1 + tid; t < 512; t += 64) {
        int lp = lab[t - 1], lc = lab[t];
        local += tr[lp * 24 + lc] + e0[t * 24 + lc];
    }
    red[tid] = local;
    if (tid < 24) { float v = start_t[tid] + e0[tid]; lse[tid] = v; vit[tid] = v; }
    __syncthreads();
    if (tid == 0) {
        float s = 0.f;
        for (int i = 0; i < 64; i++) s += red[i];
        int l0 = lab[0], lN = lab[511];
        s_num = s + start_t[l0] + e0[l0] + end_t[lN];
    }
    __syncthreads();

    for (int t = 1; t < 512; t++) {
        const float* e = e0 + t * 24;
        float nl = 0.f, nv = 0.f;
        int bi = 0;
        if (tid < 24) {
            int j = tid;
            float m = -1e30f;
#pragma unroll
            for (int i = 0; i < 24; i++) m = fmaxf(m, lse[i] + tr[i * 24 + j]);
            float s = 0.f;
#pragma unroll
            for (int i = 0; i < 24; i++) s += __expf(lse[i] + tr[i * 24 + j] - m);
            nl = m + __logf(s) + e[j];
        } else if (tid >= 32 && tid < 56) {
            int j = tid - 32;
            float bm = -1e30f;
#pragma unroll
            for (int i = 0; i < 24; i++) {
                float v = vit[i] + tr[i * 24 + j];
                if (v > bm) { bm = v; bi = i; }   // strict > : first-max like jnp.argmax
            }
            nv = bm + e[j];
        }
        __syncthreads();
        if (tid < 24) lse[tid] = nl;
        else if (tid >= 32 && tid < 56) {
            vit[tid - 32] = nv;
            hist[(t - 1) * 24 + (tid - 32)] = (unsigned char)bi;
        }
        __syncthreads();
    }

    if (tid == 0) {
        float m = -1e30f;
        for (int j = 0; j < 24; j++) m = fmaxf(m, lse[j] + end_t[j]);
        float s = 0.f;
        for (int j = 0; j < 24; j++) s += __expf(lse[j] + end_t[j] - m);
        float den = m + __logf(s);
        llh_part[b] = s_num - den;
    }
    if (tid == 32) {
        float bm = -1e30f;
        int last = 0;
        for (int j = 0; j < 24; j++) {
            float v = vit[j] + end_t[j];
            if (v > bm) { bm = v; last = j; }
        }
        out_crf[b * 512 + 511] = (float)last;
        int tag = last;
        for (int t = 510; t >= 0; t--) {
            tag = hist[t * 24 + tag];
            out_crf[b * 512 + t] = (float)tag;
        }
    }
}

__global__ void finalize_kernel(const float* __restrict__ llh_part, float* __restrict__ out_scalar)
{
    if (threadIdx.x == 0) {
        float s = 0.f;
        for (int i = 0; i < 32; i++) s += llh_part[i];
        *out_scalar = -s / 16384.0f;
    }
}

// --------------------------------- launch -------------------------------------
extern "C" void kernel_launch(void* const* d_in, const int* in_sizes, int n_in,
                              void* d_out, int out_size)
{
    const float* enc     = (const float*)d_in[0];   // (32,512,512)
    const int*   labels  = (const int*)d_in[1];     // (32,512)
    // d_in[2] = mask (all ones) — unused
    const float* Win     = (const float*)d_in[3];   // (1536,512)
    const float* bin_    = (const float*)d_in[4];   // (1536,)
    const float* Wout    = (const float*)d_in[5];   // (512,512)
    const float* bout    = (const float*)d_in[6];   // (512,)
    const float* crf_w   = (const float*)d_in[7];   // (24,512)
    const float* crf_b   = (const float*)d_in[8];   // (24,)
    const float* start_t = (const float*)d_in[9];   // (24,)
    const float* end_t   = (const float*)d_in[10];  // (24,)
    const float* trans   = (const float*)d_in[11];  // (24,24)
    const float* ent_w   = (const float*)d_in[12];  // (2,512)
    const float* ent_b   = (const float*)d_in[13];  // (2,)

    float* out = (float*)d_out;  // [crf_out 16384 | seg_out 32768 | -llh 1]

    float *qkv, *scores, *attn, *dec, *em, *llh;
    cudaGetSymbolAddress((void**)&qkv, g_qkv);
    cudaGetSymbolAddress((void**)&scores, g_scores);
    cudaGetSymbolAddress((void**)&attn, g_attn);
    cudaGetSymbolAddress((void**)&dec, g_dec);
    cudaGetSymbolAddress((void**)&em, g_em);
    cudaGetSymbolAddress((void**)&llh, g_llh);

    cudaFuncSetAttribute(mma_gemm_kernel,
                         cudaFuncAttributeMaxDynamicSharedMemorySize, SMEM_BYTES);

    // 1) QKV = enc @ Win^T + bin : (16384 x 1536), K=512
    mma_gemm_kernel<<<dim3(12, 128, 1), 256, SMEM_BYTES>>>(
        enc, 512, 0, 0,
        Win, 512, 0, 0,
        qkv, 1536, 0, 0,
        bin_, 512, 1.0f, /*transB*/1, 1);

    // 2) scores[b,h] = Q @ K^T / 16 : 64 batched (512 x 512), K=256
    mma_gemm_kernel<<<dim3(4, 4, 64), 256, SMEM_BYTES>>>(
        qkv,        1536, 512LL * 1536, 256,
        qkv + 512,  1536, 512LL * 1536, 256,
        scores,     512,  524288LL,     262144LL,
        nullptr, 256, 0.0625f, /*transB*/1, 2);

    // 3) softmax over rows
    softmax_rows<<<4096, 256>>>(scores);

    // 4) attn_out[b,h] = P @ V : 64 batched (512 x 256), K=512
    mma_gemm_kernel<<<dim3(2, 4, 64), 256, SMEM_BYTES>>>(
        scores,      512,  524288LL,     262144LL,
        qkv + 1024,  1536, 512LL * 1536, 256,
        attn,        512,  262144LL,     256LL,
        nullptr, 512, 1.0f, /*transB=0*/0, 2);

    // 5) dec = relu(attn @ Wout^T + bout) : (16384 x 512), K=512
    mma_gemm_kernel<<<dim3(4, 128, 1), 256, SMEM_BYTES>>>(
        attn, 512, 0, 0,
        Wout, 512, 0, 0,
        dec,  512, 0, 0,
        bout, 512, 1.0f, /*transB|relu*/3, 1);

    // 6) emissions (24) + seg log-softmax (2); seg written straight into d_out
    emissions_kernel<<<2048, 256>>>(dec, crf_w, crf_b, ent_w, ent_b, em, out + 16384);

    // 7) CRF scan: numerator + normalizer + Viterbi (+ backtrack into d_out)
    crf_kernel<<<32, 64>>>(em, labels, start_t, end_t, trans, out, llh);

    // 8) scalar -llh
    finalize_kernel<<<1, 32>>>(llh, out + 16384 + 32768);
}